// round 1
// baseline (speedup 1.0000x reference)
#include <cuda_runtime.h>
#include <cstdint>
#include <cstddef>

// ---------------- problem constants ----------------
namespace cfg {
constexpr int B  = 512;
constexpr int C  = 200;
constexpr int E  = 128;
constexpr int CV = 384;
constexpr int F  = 384;          // 3E
constexpr int CTILE = 40;        // contexts per block (C = 5 * 40)
constexpr int NCT   = C / CTILE; // 5
constexpr int TXN = 48;          // v-thread dim (384 = 48*8 outputs / thread)
constexpr int TYN = 5;           // c-thread dim (40 = 5*8)
constexpr int NTHREADS = TXN * TYN; // 240
constexpr int KCHUNK = 16;
constexpr int NKCH = F / KCHUNK; // 24
constexpr int CTXPAD = 44;       // padded row length for ctx[k][c]
constexpr int SM_CTX = F * CTXPAD;   // 16896 floats
constexpr int SM_WC  = KCHUNK * CV;  // 6144 floats (reused as reduction buf)
constexpr int SMEM_FLOATS = SM_CTX + SM_WC + 128; // +128 floats for idx area
constexpr size_t SMEM_BYTES = (size_t)SMEM_FLOATS * 4; // ~92.7 KB
}

// ---------------- device scratch (no runtime allocation allowed) ------------
__device__ float g_Wt[cfg::F * cfg::CV];                       // Wt[k][v] = W[v][k]
__device__ float g_h[(size_t)cfg::B * cfg::C * cfg::CV];       // tanh activations
__device__ float g_scores[cfg::B * cfg::C];                    // pre-softmax scores

// ---------------- f32x2 packed-FMA helpers (sm_100+ PTX) --------------------
__device__ __forceinline__ void fma2(unsigned long long& d,
                                     unsigned long long a_,
                                     unsigned long long b_) {
    asm("fma.rn.f32x2 %0, %1, %2, %0;" : "+l"(d) : "l"(a_), "l"(b_));
}
__device__ __forceinline__ unsigned long long bcast2(float x) {
    unsigned long long r;
    asm("mov.b64 %0, {%1, %1};" : "=l"(r) : "f"(x));
    return r;
}
__device__ __forceinline__ void unpack2(unsigned long long p, float& lo, float& hi) {
    asm("mov.b64 {%0, %1}, %2;" : "=f"(lo), "=f"(hi) : "l"(p));
}

// ---------------- kernel 0: transpose W [CV,F] -> Wt [F,CV] -----------------
__global__ void wt_transpose_kernel(const float* __restrict__ W) {
    __shared__ float tile[32][33];
    int k = blockIdx.x * 32 + threadIdx.x;
    int v = blockIdx.y * 32 + threadIdx.y;
    tile[threadIdx.y][threadIdx.x] = W[(size_t)v * cfg::F + k];
    __syncthreads();
    int ko = blockIdx.x * 32 + threadIdx.y;
    int vo = blockIdx.y * 32 + threadIdx.x;
    g_Wt[(size_t)ko * cfg::CV + vo] = tile[threadIdx.x][threadIdx.y];
}

// ---------------- kernel 1: gather + GEMM(tanh) + scores --------------------
__global__ void __launch_bounds__(cfg::NTHREADS)
k1_gemm_kernel(const int* __restrict__ starts,
               const int* __restrict__ paths,
               const int* __restrict__ ends,
               const float* __restrict__ node_emb,
               const float* __restrict__ path_emb,
               const float* __restrict__ avec) {
    using namespace cfg;
    const int b  = blockIdx.y;
    const int ct = blockIdx.x;
    const int tid = threadIdx.x;
    const int tx = tid % TXN;       // v group
    const int ty = tid / TXN;       // c group

    extern __shared__ float sm[];
    float* sctx = sm;                       // [F][CTXPAD]
    float* sWc  = sm + SM_CTX;              // [KCHUNK][CV], reused later
    int*   sidx = (int*)(sWc + SM_WC);      // 120 indices

    const int cbase = ct * CTILE;

    // ---- load the 120 indices for this tile ----
    if (tid < 3 * CTILE) {
        int sec = tid / CTILE, c = tid % CTILE;
        int gi = b * C + cbase + c;
        int idx;
        if (sec == 0)      idx = starts[gi];
        else if (sec == 1) idx = paths[gi];
        else               idx = ends[gi];
        sidx[tid] = idx;
    }
    __syncthreads();

    // ---- gather s|p|e rows into ctx[k][c] (transposed, padded) ----
    // task = jj*120 + sec*40 + c  -> consecutive threads write consecutive c
    // (stride-1 smem stores: conflict-free)
    {
        const float4* node4 = (const float4*)node_emb;
        const float4* path4 = (const float4*)path_emb;
        #pragma unroll
        for (int it = 0; it < 16; ++it) {
            int task = tid + it * NTHREADS;          // 0..3839
            int c   = task % CTILE;
            int rem = task / CTILE;
            int sec = rem % 3;
            int jj  = rem / 3;                       // 0..31 (float4 within row)
            int idx = sidx[sec * CTILE + c];
            const float4* src = (sec == 1) ? path4 : node4;
            float4 val = __ldg(&src[(size_t)idx * (E / 4) + jj]);
            int kb = sec * E + jj * 4;
            sctx[(kb + 0) * CTXPAD + c] = val.x;
            sctx[(kb + 1) * CTXPAD + c] = val.y;
            sctx[(kb + 2) * CTXPAD + c] = val.z;
            sctx[(kb + 3) * CTXPAD + c] = val.w;
        }
    }

    // ---- main GEMM: 8v x 8c register tile per thread, f32x2 accumulators ----
    // v indices: group A = tx*4 + {0..3}, group B = 192 + tx*4 + {0..3}
    // c indices: cbase + ty*8 + {0..7}
    unsigned long long acc[4][8];
    #pragma unroll
    for (int vp = 0; vp < 4; ++vp)
        #pragma unroll
        for (int j = 0; j < 8; ++j) acc[vp][j] = 0ull;

    const float4* Wt4 = (const float4*)g_Wt;

    for (int kc = 0; kc < NKCH; ++kc) {
        __syncthreads();
        // stage 16 contiguous rows of Wt (k-major) -> conflict-free float4 copy
        {
            const float4* src = Wt4 + (size_t)kc * (KCHUNK * CV / 4);
            float4* dst = (float4*)sWc;
            #pragma unroll
            for (int i = tid; i < KCHUNK * CV / 4; i += NTHREADS) dst[i] = src[i];
        }
        __syncthreads();

        #pragma unroll 4
        for (int kk = 0; kk < KCHUNK; ++kk) {
            const int k = kc * KCHUNK + kk;
            // W: two 16B loads give 4 v-pairs directly (no packing movs)
            const ulonglong2* wrow = (const ulonglong2*)(sWc + kk * CV);
            ulonglong2 wA = wrow[tx];        // v = tx*4 .. tx*4+3
            ulonglong2 wB = wrow[TXN + tx];  // v = 192 + tx*4 ..
            unsigned long long wp0 = wA.x, wp1 = wA.y, wp2 = wB.x, wp3 = wB.y;
            // ctx: 8 scalars (broadcast within warp), packed per-c
            const float4* crow = (const float4*)(sctx + k * CTXPAD);
            float4 c0 = crow[ty * 2];
            float4 c1 = crow[ty * 2 + 1];
            float cs[8] = {c0.x, c0.y, c0.z, c0.w, c1.x, c1.y, c1.z, c1.w};
            #pragma unroll
            for (int j = 0; j < 8; ++j) {
                unsigned long long cp = bcast2(cs[j]);
                fma2(acc[0][j], wp0, cp);
                fma2(acc[1][j], wp1, cp);
                fma2(acc[2][j], wp2, cp);
                fma2(acc[3][j], wp3, cp);
            }
        }
    }

    // ---- epilogue: tanh, store h, deterministic score reduction ----
    float hv[8][8]; // hv[vi][c]
    #pragma unroll
    for (int vp = 0; vp < 4; ++vp)
        #pragma unroll
        for (int j = 0; j < 8; ++j) {
            float lo, hi;
            unpack2(acc[vp][j], lo, hi);
            hv[2 * vp + 0][j] = tanhf(lo);
            hv[2 * vp + 1][j] = tanhf(hi);
        }

    // a values for this thread's 8 v's
    const float4* a4 = (const float4*)avec;
    float4 aA = __ldg(&a4[tx]);
    float4 aB = __ldg(&a4[TXN + tx]);
    float av[8] = {aA.x, aA.y, aA.z, aA.w, aB.x, aB.y, aB.z, aB.w};

    __syncthreads();           // done reading sWc; reuse as reduction buffer
    float* red = sWc;          // [CTILE][TXN]

    #pragma unroll
    for (int j = 0; j < 8; ++j) {
        int cl = ty * 8 + j;                     // 0..39
        int cg = cbase + cl;
        float4 hA = make_float4(hv[0][j], hv[1][j], hv[2][j], hv[3][j]);
        float4 hB = make_float4(hv[4][j], hv[5][j], hv[6][j], hv[7][j]);
        float4* dst = (float4*)(g_h + (size_t)(b * C + cg) * CV);
        dst[tx]       = hA;     // v = tx*4..
        dst[TXN + tx] = hB;     // v = 192 + tx*4..
        float p = 0.f;
        #pragma unroll
        for (int vi = 0; vi < 8; ++vi) p += hv[vi][j] * av[vi];
        red[cl * TXN + tx] = p;
    }
    __syncthreads();

    if (tid < CTILE) {
        float s = 0.f;
        #pragma unroll 8
        for (int j = 0; j < TXN; ++j) s += red[tid * TXN + j];  // fixed order
        g_scores[b * C + cbase + tid] = s;
    }
}

// ---------------- kernel 2: softmax over C + weighted sum -------------------
__global__ void __launch_bounds__(cfg::CV)
k2_softmax_kernel(float* __restrict__ out) {
    using namespace cfg;
    const int b = blockIdx.x;
    const int tid = threadIdx.x;

    __shared__ float sc[C];
    __shared__ float attn[C];
    __shared__ float red[32];
    __shared__ float s_max, s_sum;

    if (tid < C) sc[tid] = g_scores[b * C + tid];
    __syncthreads();

    if (tid < 32) {
        float m = -3.4e38f;
        for (int c = tid; c < C; c += 32) m = fmaxf(m, sc[c]);
        red[tid] = m;
    }
    __syncthreads();
    if (tid == 0) {
        float m = red[0];
        #pragma unroll
        for (int j = 1; j < 32; ++j) m = fmaxf(m, red[j]);
        s_max = m;
    }
    __syncthreads();
    if (tid < 32) {
        float s = 0.f;
        for (int c = tid; c < C; c += 32) s += expf(sc[c] - s_max);
        red[tid] = s;
    }
    __syncthreads();
    if (tid == 0) {
        float s = 0.f;
        #pragma unroll
        for (int j = 0; j < 32; ++j) s += red[j];
        s_sum = s;
    }
    __syncthreads();
    if (tid < C) attn[tid] = expf(sc[tid] - s_max) / s_sum;
    __syncthreads();

    // out[b][v] = sum_c attn[c] * h[b][c][v]   (coalesced over v = tid)
    const float* hb = g_h + (size_t)b * C * CV;
    const int v = tid;
    float a0 = 0.f, a1 = 0.f, a2 = 0.f, a3 = 0.f;
    #pragma unroll 4
    for (int c = 0; c < C; c += 4) {
        a0 = fmaf(attn[c + 0], hb[(size_t)(c + 0) * CV + v], a0);
        a1 = fmaf(attn[c + 1], hb[(size_t)(c + 1) * CV + v], a1);
        a2 = fmaf(attn[c + 2], hb[(size_t)(c + 2) * CV + v], a2);
        a3 = fmaf(attn[c + 3], hb[(size_t)(c + 3) * CV + v], a3);
    }
    out[(size_t)b * CV + v] = (a0 + a1) + (a2 + a3);
}

// ---------------- launch ----------------------------------------------------
extern "C" void kernel_launch(void* const* d_in, const int* in_sizes, int n_in,
                              void* d_out, int out_size) {
    (void)in_sizes; (void)n_in; (void)out_size;
    const int*   starts   = (const int*)d_in[0];
    const int*   paths    = (const int*)d_in[1];
    const int*   ends     = (const int*)d_in[2];
    /* masks d_in[3] unused by the reference */
    const float* node_emb = (const float*)d_in[4];
    const float* path_emb = (const float*)d_in[5];
    const float* W        = (const float*)d_in[6];
    const float* avec     = (const float*)d_in[7];
    float* out = (float*)d_out;

    cudaFuncSetAttribute(k1_gemm_kernel,
                         cudaFuncAttributeMaxDynamicSharedMemorySize,
                         (int)cfg::SMEM_BYTES);

    wt_transpose_kernel<<<dim3(cfg::F / 32, cfg::CV / 32), dim3(32, 32)>>>(W);
    k1_gemm_kernel<<<dim3(cfg::NCT, cfg::B), cfg::NTHREADS, cfg::SMEM_BYTES>>>(
        starts, paths, ends, node_emb, path_emb, avec);
    k2_softmax_kernel<<<cfg::B, cfg::CV>>>(out);
}

// round 3
// speedup vs baseline: 1.4074x; 1.4074x over previous
#include <cuda_runtime.h>
#include <cstdint>
#include <cstddef>

// ============================ problem constants =============================
namespace cfg {
constexpr int B  = 512;
constexpr int C  = 200;
constexpr int E  = 128;
constexpr int CV = 384;
constexpr int F  = 384;                 // K dim (3E)
constexpr int ROWS = B * C;             // 102400
constexpr int MT = 128;                 // rows per CTA
constexpr int NTILES = ROWS / MT;       // 800
constexpr int NTH = 256;                // 8 warps: 4 (M) x 2 (N)

constexpr int APAD = 392;               // 384 + 8 (bf16), stride 784 B
constexpr int BPAD = 40;                // 32 + 8  (bf16), stride 80 B

// dynamic smem layout (bytes)
constexpr uint32_t A_HI = 0;                         // [128][392] bf16 = 100352
constexpr uint32_t A_LO = 100352;                    // 100352
constexpr uint32_t B_HI = 200704;                    // [128][40] bf16 = 10240
constexpr uint32_t B_LO = 210944;                    // 10240
constexpr uint32_t IDX  = 221184;                    // 384 ints = 1536
constexpr uint32_t RED  = 222720;                    // 128 floats = 512
constexpr uint32_t SMEM_BYTES = 223232;
}

// ===================== device scratch (no runtime alloc) ====================
__device__ uint32_t g_Whi[cfg::CV * cfg::F / 2];     // bf16 pairs, [v][k] row-major
__device__ uint32_t g_Wlo[cfg::CV * cfg::F / 2];
__device__ float    g_h[(size_t)cfg::ROWS * cfg::CV];
__device__ float    g_scores[cfg::ROWS];

// ============================== PTX helpers =================================
__device__ __forceinline__ uint32_t smem_u32(const void* p) {
    uint32_t a;
    asm("{ .reg .u64 t; cvta.to.shared.u64 t, %1; cvt.u32.u64 %0, t; }" : "=r"(a) : "l"(p));
    return a;
}
__device__ __forceinline__ void ldsm_x4(uint32_t (&r)[4], uint32_t addr) {
    asm volatile("ldmatrix.sync.aligned.m8n8.x4.shared.b16 {%0,%1,%2,%3}, [%4];"
                 : "=r"(r[0]), "=r"(r[1]), "=r"(r[2]), "=r"(r[3]) : "r"(addr));
}
__device__ __forceinline__ void mma_bf16(float (&d)[4], const uint32_t (&a)[4],
                                         uint32_t b0, uint32_t b1) {
    asm volatile(
        "mma.sync.aligned.m16n8k16.row.col.f32.bf16.bf16.f32 "
        "{%0,%1,%2,%3}, {%4,%5,%6,%7}, {%8,%9}, {%0,%1,%2,%3};"
        : "+f"(d[0]), "+f"(d[1]), "+f"(d[2]), "+f"(d[3])
        : "r"(a[0]), "r"(a[1]), "r"(a[2]), "r"(a[3]), "r"(b0), "r"(b1));
}
// bf16 split: pack (even->low, odd->high), rn rounding
__device__ __forceinline__ uint32_t pack_bf16(float k_even, float k_odd) {
    uint32_t r;
    asm("cvt.rn.bf16x2.f32 %0, %1, %2;" : "=r"(r) : "f"(k_odd), "f"(k_even));
    return r;
}
__device__ __forceinline__ float bf_lo(uint32_t w) { return __uint_as_float(w << 16); }
__device__ __forceinline__ float bf_hi(uint32_t w) { return __uint_as_float(w & 0xFFFF0000u); }

// ================= kernel 0: W fp32 -> bf16 hi/lo ([v][k] row-major) ========
__global__ void __launch_bounds__(256)
wconv_kernel(const float* __restrict__ W) {
    int i = blockIdx.x * 256 + threadIdx.x;          // float4 id, 36864 total
    float4 x = ((const float4*)W)[i];
    uint32_t h01 = pack_bf16(x.x, x.y);
    uint32_t h23 = pack_bf16(x.z, x.w);
    float r0 = x.x - bf_lo(h01), r1 = x.y - bf_hi(h01);
    float r2 = x.z - bf_lo(h23), r3 = x.w - bf_hi(h23);
    ((uint2*)g_Whi)[i] = make_uint2(h01, h23);
    ((uint2*)g_Wlo)[i] = make_uint2(pack_bf16(r0, r1), pack_bf16(r2, r3));
}

// ====== kernel 1: gather + bf16x3 HMMA GEMM + tanh + h + scores =============
__global__ void __launch_bounds__(cfg::NTH, 1)
k1_mma_kernel(const int* __restrict__ starts,
              const int* __restrict__ paths,
              const int* __restrict__ ends,
              const float* __restrict__ node_emb,
              const float* __restrict__ path_emb,
              const float* __restrict__ avec) {
    using namespace cfg;
    extern __shared__ char smem[];
    const uint32_t sb = smem_u32(smem);
    const int tid = threadIdx.x;
    const int wid = tid >> 5, lane = tid & 31;
    const int wm = wid & 3;          // M slice (32 rows)
    const int wn = wid >> 2;         // N slice (64 cols of current 128-chunk)
    const int tile = blockIdx.x;
    int* sidx = (int*)(smem + IDX);
    float* red = (float*)(smem + RED);

    // ---- indices ----
    if (tid < 128) {
        int r = tile * 128 + tid;
        sidx[tid]       = starts[r];
        sidx[128 + tid] = paths[r];
        sidx[256 + tid] = ends[r];
    }
    __syncthreads();

    // ---- gather ctx rows, split fp32 -> bf16 hi/lo into padded A ----
    #pragma unroll 2
    for (int i = 0; i < 48; ++i) {
        int task = tid + i * 256;                    // 0..12287
        int j = task & 31;                           // float4 within 128-elem row
        int rem = task >> 5;
        int seg = rem % 3, row = rem / 3;
        int idx = sidx[seg * 128 + row];
        const float4* src = (seg == 1) ? (const float4*)path_emb
                                       : (const float4*)node_emb;
        float4 x = __ldg(src + (size_t)idx * 32 + j);
        uint32_t h01 = pack_bf16(x.x, x.y);
        uint32_t h23 = pack_bf16(x.z, x.w);
        float r0 = x.x - bf_lo(h01), r1 = x.y - bf_hi(h01);
        float r2 = x.z - bf_lo(h23), r3 = x.w - bf_hi(h23);
        int k = seg * 128 + j * 4;
        uint32_t off = (uint32_t)row * (APAD * 2) + (uint32_t)k * 2;
        *(uint2*)(smem + A_HI + off) = make_uint2(h01, h23);
        *(uint2*)(smem + A_LO + off) = make_uint2(pack_bf16(r0, r1), pack_bf16(r2, r3));
    }

    // ---- precompute ldmatrix lane addresses ----
    // A: rows = wm*32 + mi*16 + (lane&15), k-half = (lane>>4)*8
    const uint32_t a_lane = sb + (uint32_t)(wm * 32 + (lane & 15)) * (APAD * 2)
                          + (uint32_t)(lane >> 4) * 16;
    // B: groups of 8 lanes -> (n8-tile parity, k-half)
    const int bgrp = lane >> 3;
    const uint32_t b_lane_n = (uint32_t)(((bgrp & 2) << 2) + (lane & 7)); // 0..15
    const uint32_t b_lane_k = (uint32_t)((bgrp & 1) * 16);                // bytes
    const uint32_t b_lane = sb + b_lane_n * (BPAD * 2) + b_lane_k;

    float sc[2][2] = {{0.f, 0.f}, {0.f, 0.f}};       // score partials [mi][rowhalf]
    const size_t rowbase = (size_t)tile * 128;

    for (int nt = 0; nt < 3; ++nt) {
        float acc[2][8][4];
        #pragma unroll
        for (int mi = 0; mi < 2; ++mi)
            #pragma unroll
            for (int ni = 0; ni < 8; ++ni)
                #pragma unroll
                for (int q = 0; q < 4; ++q) acc[mi][ni][q] = 0.f;

        for (int kc = 0; kc < 12; ++kc) {
            __syncthreads();                         // prev B chunk consumed
            // stage B chunk: [128 n][32 k] bf16, hi+lo
            #pragma unroll
            for (int i = 0; i < 4; ++i) {
                int task = tid + i * 256;            // 0..1023
                int mat = task >> 9;
                int rem = task & 511;
                int n = rem >> 2, g = rem & 3;       // g: 8-bf16 granule of k
                const uint4* src = (const uint4*)(mat ? g_Wlo : g_Whi);
                uint4 v = src[(nt * 128 + n) * 48 + kc * 4 + g];
                *(uint4*)(smem + (mat ? B_LO : B_HI) + n * (BPAD * 2) + g * 16) = v;
            }
            __syncthreads();

            #pragma unroll
            for (int s = 0; s < 2; ++s) {            // two k16 steps
                const uint32_t akoff = (uint32_t)(kc * 32 + s * 16) * 2;
                uint32_t ah[2][4], al[2][4];
                #pragma unroll
                for (int mi = 0; mi < 2; ++mi) {
                    ldsm_x4(ah[mi], a_lane + A_HI + mi * (16 * APAD * 2) + akoff);
                    ldsm_x4(al[mi], a_lane + A_LO + mi * (16 * APAD * 2) + akoff);
                }
                uint32_t bh[8][2], bl[8][2];
                #pragma unroll
                for (int bj = 0; bj < 4; ++bj) {
                    const uint32_t bn = (uint32_t)(wn * 64 + bj * 16) * (BPAD * 2)
                                      + (uint32_t)(s * 32);
                    uint32_t r[4];
                    ldsm_x4(r, b_lane + B_HI + bn);
                    bh[2*bj][0] = r[0]; bh[2*bj][1] = r[1];
                    bh[2*bj+1][0] = r[2]; bh[2*bj+1][1] = r[3];
                    ldsm_x4(r, b_lane + B_LO + bn);
                    bl[2*bj][0] = r[0]; bl[2*bj][1] = r[1];
                    bl[2*bj+1][0] = r[2]; bl[2*bj+1][1] = r[3];
                }
                // combo 0: A_hi * B_hi
                #pragma unroll
                for (int mi = 0; mi < 2; ++mi)
                    #pragma unroll
                    for (int ni = 0; ni < 8; ++ni)
                        mma_bf16(acc[mi][ni], ah[mi], bh[ni][0], bh[ni][1]);
                // combo 1: A_hi * B_lo
                #pragma unroll
                for (int mi = 0; mi < 2; ++mi)
                    #pragma unroll
                    for (int ni = 0; ni < 8; ++ni)
                        mma_bf16(acc[mi][ni], ah[mi], bl[ni][0], bl[ni][1]);
                // combo 2: A_lo * B_hi
                #pragma unroll
                for (int mi = 0; mi < 2; ++mi)
                    #pragma unroll
                    for (int ni = 0; ni < 8; ++ni)
                        mma_bf16(acc[mi][ni], al[mi], bh[ni][0], bh[ni][1]);
            }
        }

        // ---- epilogue for this 128-col chunk: tanh, h store, score partials --
        #pragma unroll
        for (int mi = 0; mi < 2; ++mi) {
            const int r0 = wm * 32 + mi * 16 + (lane >> 2);
            #pragma unroll
            for (int ni = 0; ni < 8; ++ni) {
                const int v0 = nt * 128 + wn * 64 + ni * 8 + (lane & 3) * 2;
                const float a0v = __ldg(avec + v0);
                const float a1v = __ldg(avec + v0 + 1);
                float h00 = tanhf(acc[mi][ni][0]);
                float h01 = tanhf(acc[mi][ni][1]);
                float h10 = tanhf(acc[mi][ni][2]);
                float h11 = tanhf(acc[mi][ni][3]);
                *(float2*)(g_h + (rowbase + r0) * 384 + v0)     = make_float2(h00, h01);
                *(float2*)(g_h + (rowbase + r0 + 8) * 384 + v0) = make_float2(h10, h11);
                sc[mi][0] += h00 * a0v + h01 * a1v;
                sc[mi][1] += h10 * a0v + h11 * a1v;
            }
        }
    }

    // ---- score reduction: quad shfl, then cross-warp over wn ----
    #pragma unroll
    for (int mi = 0; mi < 2; ++mi)
        #pragma unroll
        for (int j = 0; j < 2; ++j) {
            float s = sc[mi][j];
            s += __shfl_xor_sync(0xFFFFFFFFu, s, 1);
            s += __shfl_xor_sync(0xFFFFFFFFu, s, 2);
            sc[mi][j] = s;
        }
    __syncthreads();
    if (wn == 1 && (lane & 3) == 0) {
        #pragma unroll
        for (int mi = 0; mi < 2; ++mi)
            #pragma unroll
            for (int j = 0; j < 2; ++j)
                red[wm * 32 + mi * 16 + j * 8 + (lane >> 2)] = sc[mi][j];
    }
    __syncthreads();
    if (wn == 0 && (lane & 3) == 0) {
        #pragma unroll
        for (int mi = 0; mi < 2; ++mi)
            #pragma unroll
            for (int j = 0; j < 2; ++j) {
                int lr = wm * 32 + mi * 16 + j * 8 + (lane >> 2);
                g_scores[rowbase + lr] = sc[mi][j] + red[lr];
            }
    }
}

// ================= kernel 2: softmax over C + weighted sum ==================
__global__ void __launch_bounds__(cfg::CV)
k2_softmax_kernel(float* __restrict__ out) {
    using namespace cfg;
    const int b = blockIdx.x;
    const int tid = threadIdx.x;

    __shared__ float sc[C];
    __shared__ float attn[C];
    __shared__ float red[32];
    __shared__ float s_max, s_sum;

    if (tid < C) sc[tid] = g_scores[b * C + tid];
    __syncthreads();

    if (tid < 32) {
        float m = -3.4e38f;
        for (int c = tid; c < C; c += 32) m = fmaxf(m, sc[c]);
        red[tid] = m;
    }
    __syncthreads();
    if (tid == 0) {
        float m = red[0];
        #pragma unroll
        for (int j = 1; j < 32; ++j) m = fmaxf(m, red[j]);
        s_max = m;
    }
    __syncthreads();
    if (tid < 32) {
        float s = 0.f;
        for (int c = tid; c < C; c += 32) s += expf(sc[c] - s_max);
        red[tid] = s;
    }
    __syncthreads();
    if (tid == 0) {
        float s = 0.f;
        #pragma unroll
        for (int j = 0; j < 32; ++j) s += red[j];
        s_sum = s;
    }
    __syncthreads();
    if (tid < C) attn[tid] = expf(sc[tid] - s_max) / s_sum;
    __syncthreads();

    const float* hb = g_h + (size_t)b * C * CV;
    const int v = tid;
    float a0 = 0.f, a1 = 0.f, a2 = 0.f, a3 = 0.f;
    #pragma unroll 4
    for (int c = 0; c < C; c += 4) {
        a0 = fmaf(attn[c + 0], hb[(size_t)(c + 0) * CV + v], a0);
        a1 = fmaf(attn[c + 1], hb[(size_t)(c + 1) * CV + v], a1);
        a2 = fmaf(attn[c + 2], hb[(size_t)(c + 2) * CV + v], a2);
        a3 = fmaf(attn[c + 3], hb[(size_t)(c + 3) * CV + v], a3);
    }
    out[(size_t)b * CV + v] = (a0 + a1) + (a2 + a3);
}

// ================================ launch =====================================
extern "C" void kernel_launch(void* const* d_in, const int* in_sizes, int n_in,
                              void* d_out, int out_size) {
    (void)in_sizes; (void)n_in; (void)out_size;
    const int*   starts   = (const int*)d_in[0];
    const int*   paths    = (const int*)d_in[1];
    const int*   ends     = (const int*)d_in[2];
    /* masks d_in[3] unused by the reference */
    const float* node_emb = (const float*)d_in[4];
    const float* path_emb = (const float*)d_in[5];
    const float* W        = (const float*)d_in[6];
    const float* avec     = (const float*)d_in[7];
    float* out = (float*)d_out;

    cudaFuncSetAttribute(k1_mma_kernel,
                         cudaFuncAttributeMaxDynamicSharedMemorySize,
                         (int)cfg::SMEM_BYTES);

    wconv_kernel<<<cfg::CV * cfg::F / 4 / 256, 256>>>(W);
    k1_mma_kernel<<<cfg::NTILES, cfg::NTH, cfg::SMEM_BYTES>>>(
        starts, paths, ends, node_emb, path_emb, avec);
    k2_softmax_kernel<<<cfg::B, cfg::CV>>>(out);
}